// round 10
// baseline (speedup 1.0000x reference)
#include <cuda_runtime.h>
#include <cuda_bf16.h>
#include <cstdint>
#include <cstddef>

#define BB    16
#define LQ    1024
#define EMBED 768
#define NH    12
#define NL    3
#define NP    4
#define DV    384
#define DH    32
#define LKV   5376
#define NOFF  288
#define NAW   144
#define NPK   432

// ---------------- scratch (device globals; no allocation) ----------------
__device__ __nv_bfloat16 g_qn   [(size_t)BB * LQ  * EMBED];
__device__ __nv_bfloat16 g_kvn  [(size_t)BB * LKV * EMBED];
__device__ __nv_bfloat16 g_value[(size_t)BB * LKV * DV];
__device__ float         g_offaw[(size_t)BB * LQ  * NPK];
__device__ __nv_bfloat16 g_attn [(size_t)BB * LQ  * DV];
__device__ __nv_bfloat16 g_wv[EMBED * DV];
__device__ __nv_bfloat16 g_wc[EMBED * NPK];
__device__ __nv_bfloat16 g_wo[DV * EMBED];
__device__ float         g_bc[NPK];

// ---------------- fused LayerNorm -> bf16 ----------------
__global__ void __launch_bounds__(192)
ln_bf16_kernel(const float* __restrict__ X, __nv_bfloat16* __restrict__ Y,
               const float* __restrict__ w, const float* __restrict__ b) {
    int row = blockIdx.x;
    int tid = threadIdx.x;
    float4 v = ((const float4*)(X + (size_t)row * EMBED))[tid];
    float s  = v.x + v.y + v.z + v.w;
    float sq = v.x * v.x + v.y * v.y + v.z * v.z + v.w * v.w;
    #pragma unroll
    for (int o = 16; o > 0; o >>= 1) {
        s  += __shfl_down_sync(0xffffffffu, s,  o);
        sq += __shfl_down_sync(0xffffffffu, sq, o);
    }
    __shared__ float shs[6], shq[6];
    int wid = tid >> 5, lane = tid & 31;
    if (lane == 0) { shs[wid] = s; shq[wid] = sq; }
    __syncthreads();
    float ts = 0.f, tq = 0.f;
    #pragma unroll
    for (int i = 0; i < 6; i++) { ts += shs[i]; tq += shq[i]; }
    float mu = ts * (1.f / EMBED);
    float var = tq * (1.f / EMBED) - mu * mu;
    float rs = rsqrtf(var + 1e-6f);
    float4 w4 = ((const float4*)w)[tid];
    float4 b4 = ((const float4*)b)[tid];
    __nv_bfloat162 p0 = __float22bfloat162_rn(make_float2(
        (v.x - mu) * rs * w4.x + b4.x, (v.y - mu) * rs * w4.y + b4.y));
    __nv_bfloat162 p1 = __float22bfloat162_rn(make_float2(
        (v.z - mu) * rs * w4.z + b4.z, (v.w - mu) * rs * w4.w + b4.w));
    uint2 pk = make_uint2(*(uint32_t*)&p0, *(uint32_t*)&p1);
    ((uint2*)(Y + (size_t)row * EMBED))[tid] = pk;
}

// ---------------- weight conversion / packing ----------------
__global__ void cvt_kernel(const float* __restrict__ s,
                           __nv_bfloat16* __restrict__ d, int n) {
    int i = blockIdx.x * blockDim.x + threadIdx.x;
    if (i < n) d[i] = __float2bfloat16(s[i]);
}
__global__ void pack_kernel(const float* __restrict__ wo, const float* __restrict__ wa,
                            const float* __restrict__ bo, const float* __restrict__ ba,
                            __nv_bfloat16* __restrict__ d, float* __restrict__ bc) {
    int i = blockIdx.x * blockDim.x + threadIdx.x;
    if (i < EMBED * NPK) {
        int k = i / NPK, c = i % NPK;
        float v = (c < NOFF) ? wo[k * NOFF + c] : wa[k * NAW + c - NOFF];
        d[i] = __float2bfloat16(v);
    }
    if (i < NPK) bc[i] = (i < NOFF) ? bo[i] : ba[i - NOFF];
}

// ---------------- tensor-core GEMM ----------------
__device__ __forceinline__ void ldsm_x4(uint32_t& r0, uint32_t& r1,
                                        uint32_t& r2, uint32_t& r3, uint32_t addr) {
    asm volatile("ldmatrix.sync.aligned.m8n8.x4.shared.b16 {%0,%1,%2,%3}, [%4];"
                 : "=r"(r0), "=r"(r1), "=r"(r2), "=r"(r3) : "r"(addr));
}
__device__ __forceinline__ void ldsm_x4_t(uint32_t& r0, uint32_t& r1,
                                          uint32_t& r2, uint32_t& r3, uint32_t addr) {
    asm volatile("ldmatrix.sync.aligned.m8n8.x4.trans.shared.b16 {%0,%1,%2,%3}, [%4];"
                 : "=r"(r0), "=r"(r1), "=r"(r2), "=r"(r3) : "r"(addr));
}
__device__ __forceinline__ void mma_bf16(float* c, const uint32_t* a,
                                         uint32_t b0, uint32_t b1) {
    asm volatile(
        "mma.sync.aligned.m16n8k16.row.col.f32.bf16.bf16.f32 "
        "{%0,%1,%2,%3}, {%4,%5,%6,%7}, {%8,%9}, {%0,%1,%2,%3};"
        : "+f"(c[0]), "+f"(c[1]), "+f"(c[2]), "+f"(c[3])
        : "r"(a[0]), "r"(a[1]), "r"(a[2]), "r"(a[3]), "r"(b0), "r"(b1));
}
__device__ __forceinline__ void cp16(uint32_t s, const void* g) {
    asm volatile("cp.async.cg.shared.global [%0], [%1], 16;" :: "r"(s), "l"(g));
}
__device__ __forceinline__ void cp16z(uint32_t s, const void* g, bool pred) {
    int sz = pred ? 16 : 0;
    asm volatile("cp.async.cg.shared.global [%0], [%1], 16, %2;"
                 :: "r"(s), "l"(g), "r"(sz));
}
#define CP_COMMIT() asm volatile("cp.async.commit_group;" ::: "memory")
template <int N_>
__device__ __forceinline__ void cp_wait() {
    asm volatile("cp.async.wait_group %0;" :: "n"(N_) : "memory");
}

#define SA 72
#define SB 136
#define STAGES 3
#define A_STG (128 * SA)
#define B_STG (64 * SB)
#define SMEM_BYTES ((STAGES * (A_STG + B_STG)) * 2)

// MODE 0: C fp32 = acc + bias
// MODE 1: C fp32 = resid + gamma * (acc + bias)
// MODE 2: C bf16 = acc + bias
template <int MODE>
__global__ void __launch_bounds__(256, 2)
hgemm_kernel(const __nv_bfloat16* __restrict__ A,
             const __nv_bfloat16* __restrict__ Bm,
             void* __restrict__ Cout, int M, int N, int K,
             const float* __restrict__ bias,
             const float* __restrict__ resid, const float* __restrict__ gamma) {
    extern __shared__ __nv_bfloat16 smem[];
    __nv_bfloat16* sA = smem;
    __nv_bfloat16* sB = smem + STAGES * A_STG;

    const int tid  = threadIdx.x;
    const int lane = tid & 31;
    const int wid  = tid >> 5;
    const int wm   = wid & 3;
    const int wn   = wid >> 2;
    const int row0 = blockIdx.y * 128;
    const int n0   = blockIdx.x * 128;
    const int NT   = K >> 6;

    const uint32_t sAbase = (uint32_t)__cvta_generic_to_shared(sA);
    const uint32_t sBbase = (uint32_t)__cvta_generic_to_shared(sB);

    auto load_tile = [&](int stage, int kt) {
        const int k0 = kt * 64;
        #pragma unroll
        for (int j = 0; j < 4; j++) {
            int ci = tid + j * 256;
            int ar = ci >> 3, ac = (ci & 7) * 8;
            cp16(sAbase + (uint32_t)(stage * A_STG + ar * SA + ac) * 2,
                 A + (size_t)(row0 + ar) * K + k0 + ac);
            int br = ci >> 4, bc = (ci & 15) * 8;
            int col = n0 + bc;
            cp16z(sBbase + (uint32_t)(stage * B_STG + br * SB + bc) * 2,
                  Bm + (size_t)(k0 + br) * N + col, col < N);
        }
    };

    float acc[2][8][4];
    #pragma unroll
    for (int mt = 0; mt < 2; mt++)
        #pragma unroll
        for (int n8 = 0; n8 < 8; n8++)
            #pragma unroll
            for (int j = 0; j < 4; j++) acc[mt][n8][j] = 0.f;

    #pragma unroll
    for (int s = 0; s < STAGES - 1; s++) {
        if (s < NT) load_tile(s, s);
        CP_COMMIT();
    }

    const int lr  = lane & 15;
    const int lc8 = (lane >> 4) << 3;

    for (int kt = 0; kt < NT; kt++) {
        cp_wait<STAGES - 2>();
        __syncthreads();
        if (kt + STAGES - 1 < NT)
            load_tile((kt + STAGES - 1) % STAGES, kt + STAGES - 1);
        CP_COMMIT();

        const int cur = kt % STAGES;
        const uint32_t sAb = sAbase + (uint32_t)(cur * A_STG) * 2;
        const uint32_t sBb = sBbase + (uint32_t)(cur * B_STG) * 2;

        #pragma unroll
        for (int ks = 0; ks < 4; ks++) {
            const int kcol = ks * 16;
            uint32_t a[2][4];
            #pragma unroll
            for (int mt = 0; mt < 2; mt++) {
                uint32_t addr = sAb +
                    (uint32_t)((wm * 32 + mt * 16 + lr) * SA + kcol + lc8) * 2;
                ldsm_x4(a[mt][0], a[mt][1], a[mt][2], a[mt][3], addr);
            }
            // ---- split B: load half, run 8 MMAs, load half, run 8 MMAs ----
            uint32_t b0[2][4];
            #pragma unroll
            for (int nt = 0; nt < 2; nt++) {
                uint32_t addr = sBb +
                    (uint32_t)((kcol + lr) * SB + wn * 64 + nt * 16 + lc8) * 2;
                ldsm_x4_t(b0[nt][0], b0[nt][1], b0[nt][2], b0[nt][3], addr);
            }
            uint32_t b1[2][4];
            #pragma unroll
            for (int nt = 0; nt < 2; nt++) {
                uint32_t addr = sBb +
                    (uint32_t)((kcol + lr) * SB + wn * 64 + (nt + 2) * 16 + lc8) * 2;
                ldsm_x4_t(b1[nt][0], b1[nt][1], b1[nt][2], b1[nt][3], addr);
            }
            #pragma unroll
            for (int mt = 0; mt < 2; mt++)
                #pragma unroll
                for (int n8 = 0; n8 < 4; n8++)
                    mma_bf16(acc[mt][n8], a[mt],
                             b0[n8 >> 1][(n8 & 1) * 2], b0[n8 >> 1][(n8 & 1) * 2 + 1]);
            #pragma unroll
            for (int mt = 0; mt < 2; mt++)
                #pragma unroll
                for (int n8 = 0; n8 < 4; n8++)
                    mma_bf16(acc[mt][n8 + 4], a[mt],
                             b1[n8 >> 1][(n8 & 1) * 2], b1[n8 >> 1][(n8 & 1) * 2 + 1]);
        }
    }

    #pragma unroll
    for (int mt = 0; mt < 2; mt++) {
        int r = row0 + wm * 32 + mt * 16 + (lane >> 2);
        #pragma unroll
        for (int n8 = 0; n8 < 8; n8++) {
            int c = n0 + wn * 64 + n8 * 8 + (lane & 3) * 2;
            if (c >= N) continue;
            float2 bs = *(const float2*)(bias + c);
            float v0 = acc[mt][n8][0] + bs.x;
            float v1 = acc[mt][n8][1] + bs.y;
            float v2 = acc[mt][n8][2] + bs.x;
            float v3 = acc[mt][n8][3] + bs.y;
            if (MODE == 1) {
                float2 gm = *(const float2*)(gamma + c);
                float2 r0v = *(const float2*)(resid + (size_t)r * N + c);
                float2 r1v = *(const float2*)(resid + (size_t)(r + 8) * N + c);
                float* Cf = (float*)Cout;
                *(float2*)(Cf + (size_t)r * N + c) =
                    make_float2(r0v.x + gm.x * v0, r0v.y + gm.y * v1);
                *(float2*)(Cf + (size_t)(r + 8) * N + c) =
                    make_float2(r1v.x + gm.x * v2, r1v.y + gm.y * v3);
            } else if (MODE == 2) {
                __nv_bfloat16* Cb = (__nv_bfloat16*)Cout;
                *(__nv_bfloat162*)(Cb + (size_t)r * N + c) =
                    __float22bfloat162_rn(make_float2(v0, v1));
                *(__nv_bfloat162*)(Cb + (size_t)(r + 8) * N + c) =
                    __float22bfloat162_rn(make_float2(v2, v3));
            } else {
                float* Cf = (float*)Cout;
                *(float2*)(Cf + (size_t)r * N + c) = make_float2(v0, v1);
                *(float2*)(Cf + (size_t)(r + 8) * N + c) = make_float2(v2, v3);
            }
        }
    }
}

// ---------------- deformable bilinear sampling (per batch-chunk) -----------
__global__ void __launch_bounds__(256)
sample_kernel(const __nv_bfloat16* __restrict__ value,   // (NB, LKV, NH*DH)
              const float* __restrict__ offaw,           // (NB*LQ, 432)
              const float* __restrict__ refp,            // (NB*LQ, NL, 2)
              __nv_bfloat16* __restrict__ attn)          // (NB*LQ, NH*DH)
{
    const int gw   = (blockIdx.x * blockDim.x + threadIdx.x) >> 5;
    const int lane = threadIdx.x & 31;
    const int cg   = lane >> 2;
    const int ch4  = lane & 3;
    const int h  = gw % NH;
    const int bq = gw / NH;
    const int b  = bq >> 10;

    const float* rowp = offaw + (size_t)bq * NPK;
    const float* lgp  = rowp + NOFF + h * (NL * NP);
    const float* op   = rowp + h * (NL * NP * 2);
    const float* rp   = refp + (size_t)bq * (NL * 2);

    float mx = -1e30f;
    #pragma unroll
    for (int i = 0; i < NL * NP; i++) mx = fmaxf(mx, lgp[i]);
    float ssum = 0.f;
    #pragma unroll
    for (int i = 0; i < NL * NP; i++) ssum += __expf(lgp[i] - mx);
    const float inv = 1.0f / ssum;

    float acc[8];
    #pragma unroll
    for (int j = 0; j < 8; j++) acc[j] = 0.f;

    const __nv_bfloat16* vbb = value + (size_t)b * LKV * DV + h * DH;

    #pragma unroll
    for (int i = 0; i < 6; i++) {
        const int t      = i * 8 + cg;
        const int corner = t & 3;
        const int pt     = t >> 2;
        const int l      = pt >> 2;
        const int W      = 64 >> l;
        const int st     = (l == 0) ? 0 : ((l == 1) ? 4096 : 5120);

        const float rx = rp[l * 2 + 0], ry = rp[l * 2 + 1];
        const float ox = op[pt * 2 + 0], oy = op[pt * 2 + 1];
        const float invW = 1.0f / (float)W;
        const float xx = (rx + ox * invW) * (float)W - 0.5f;
        const float yy = (ry + oy * invW) * (float)W - 0.5f;
        const float x0f = floorf(xx), y0f = floorf(yy);
        const float dx = xx - x0f, dy = yy - y0f;
        const int xi = (int)x0f + (corner & 1);
        const int yi = (int)y0f + (corner >> 1);
        const float wx = (corner & 1) ? dx : 1.f - dx;
        const float wy = (corner >> 1) ? dy : 1.f - dy;
        const float wgt = __expf(lgp[pt] - mx) * inv * wx * wy;

        if (xi >= 0 && xi < W && yi >= 0 && yi < W) {
            const uint4* p = (const uint4*)(vbb + (size_t)(st + yi * W + xi) * DV) + ch4;
            uint4 v = *p;
            const __nv_bfloat162* h2 = (const __nv_bfloat162*)&v;
            #pragma unroll
            for (int j = 0; j < 4; j++) {
                float2 f = __bfloat1622float2(h2[j]);
                acc[2 * j]     = fmaf(wgt, f.x, acc[2 * j]);
                acc[2 * j + 1] = fmaf(wgt, f.y, acc[2 * j + 1]);
            }
        }
    }

    #pragma unroll
    for (int o = 4; o <= 16; o <<= 1)
        #pragma unroll
        for (int j = 0; j < 8; j++)
            acc[j] += __shfl_xor_sync(0xffffffffu, acc[j], o);

    if (cg == 0) {
        uint4 outv;
        uint32_t* ov = (uint32_t*)&outv;
        #pragma unroll
        for (int j = 0; j < 4; j++) {
            __nv_bfloat162 pk = __float22bfloat162_rn(
                make_float2(acc[2 * j], acc[2 * j + 1]));
            ov[j] = *(uint32_t*)&pk;
        }
        *(uint4*)(attn + (size_t)gw * DH + ch4 * 8) = outv;
    }
}

// ---------------- launch ----------------
extern "C" void kernel_launch(void* const* d_in, const int* in_sizes, int n_in,
                              void* d_out, int out_size) {
    const float* q      = (const float*)d_in[0];
    const float* refp   = (const float*)d_in[1];
    const float* kv     = (const float*)d_in[2];
    const float* ln1w   = (const float*)d_in[5];
    const float* ln1b   = (const float*)d_in[6];
    const float* ln2w   = (const float*)d_in[7];
    const float* ln2b   = (const float*)d_in[8];
    const float* gamma  = (const float*)d_in[9];
    const float* w_off  = (const float*)d_in[10];
    const float* b_off  = (const float*)d_in[11];
    const float* w_aw   = (const float*)d_in[12];
    const float* b_aw   = (const float*)d_in[13];
    const float* w_val  = (const float*)d_in[14];
    const float* b_val  = (const float*)d_in[15];
    const float* w_out  = (const float*)d_in[16];
    const float* b_out  = (const float*)d_in[17];
    float* out = (float*)d_out;

    __nv_bfloat16 *gqn, *gkvn, *gv, *gattn, *gwv, *gwc, *gwo;
    float *goffaw, *gbc;
    cudaGetSymbolAddress((void**)&gqn,    g_qn);
    cudaGetSymbolAddress((void**)&gkvn,   g_kvn);
    cudaGetSymbolAddress((void**)&gv,     g_value);
    cudaGetSymbolAddress((void**)&goffaw, g_offaw);
    cudaGetSymbolAddress((void**)&gattn,  g_attn);
    cudaGetSymbolAddress((void**)&gwv,    g_wv);
    cudaGetSymbolAddress((void**)&gwc,    g_wc);
    cudaGetSymbolAddress((void**)&gwo,    g_wo);
    cudaGetSymbolAddress((void**)&gbc,    g_bc);

    static cudaStream_t s_side = nullptr;
    static cudaEvent_t ev_fork = nullptr, ev_w = nullptr, ev_join = nullptr;
    if (!s_side) {
        cudaStreamCreateWithFlags(&s_side, cudaStreamNonBlocking);
        cudaEventCreateWithFlags(&ev_fork, cudaEventDisableTiming);
        cudaEventCreateWithFlags(&ev_w,    cudaEventDisableTiming);
        cudaEventCreateWithFlags(&ev_join, cudaEventDisableTiming);
        cudaFuncSetAttribute(hgemm_kernel<0>,
            cudaFuncAttributeMaxDynamicSharedMemorySize, SMEM_BYTES);
        cudaFuncSetAttribute(hgemm_kernel<1>,
            cudaFuncAttributeMaxDynamicSharedMemorySize, SMEM_BYTES);
        cudaFuncSetAttribute(hgemm_kernel<2>,
            cudaFuncAttributeMaxDynamicSharedMemorySize, SMEM_BYTES);
    }

    const int NCHUNK = 4;
    const int CB   = BB / NCHUNK;      // 4 batches per chunk
    const int MqC  = CB * LQ;          // 4096
    const int MkvC = CB * LKV;         // 21504 (168 * 128)

    // ---- fork side stream from the capturing stream FIRST ----
    cudaEventRecord(ev_fork, 0);
    cudaStreamWaitEvent(s_side, ev_fork, 0);

    // ---- weight prep on side stream (overlaps chunk-0 LN on main) ----
    cvt_kernel<<<(EMBED * DV + 255) / 256, 256, 0, s_side>>>(w_val, gwv, EMBED * DV);
    pack_kernel<<<(EMBED * NPK + 255) / 256, 256, 0, s_side>>>(
        w_off, w_aw, b_off, b_aw, gwc, gbc);
    cvt_kernel<<<(DV * EMBED + 255) / 256, 256, 0, s_side>>>(w_out, gwo, DV * EMBED);
    cudaEventRecord(ev_w, s_side);
    cudaStreamWaitEvent(0, ev_w, 0);   // main stream's GEMMs gate on weights

    for (int c = 0; c < NCHUNK; c++) {
        cudaStream_t st = (c & 1) ? s_side : (cudaStream_t)0;
        const size_t qo  = (size_t)c * MqC;
        const size_t kvo = (size_t)c * MkvC;

        const float* qh    = q    + qo  * EMBED;
        const float* kvh   = kv   + kvo * EMBED;
        const float* refph = refp + qo  * NL * 2;
        __nv_bfloat16* qnh   = gqn   + qo  * EMBED;
        __nv_bfloat16* kvnh  = gkvn  + kvo * EMBED;
        __nv_bfloat16* gvh   = gv    + kvo * DV;
        float*         offh  = goffaw + qo * NPK;
        __nv_bfloat16* attnh = gattn + qo  * DV;
        float*         outh  = out   + qo  * EMBED;

        ln_bf16_kernel<<<MqC, 192, 0, st>>>(qh, qnh, ln1w, ln1b);
        ln_bf16_kernel<<<MkvC, 192, 0, st>>>(kvh, kvnh, ln2w, ln2b);

        hgemm_kernel<0><<<dim3((NPK + 127) / 128, MqC / 128), 256, SMEM_BYTES, st>>>(
            qnh, gwc, offh, MqC, NPK, EMBED, gbc, nullptr, nullptr);

        hgemm_kernel<2><<<dim3(DV / 128, MkvC / 128), 256, SMEM_BYTES, st>>>(
            kvnh, gwv, gvh, MkvC, DV, EMBED, b_val, nullptr, nullptr);

        sample_kernel<<<(CB * LQ * NH) / 8, 256, 0, st>>>(
            gvh, offh, refph, attnh);

        hgemm_kernel<1><<<dim3(EMBED / 128, MqC / 128), 256, SMEM_BYTES, st>>>(
            attnh, gwo, outh, MqC, EMBED, DV, b_out, qh, gamma);
    }

    cudaEventRecord(ev_join, s_side);
    cudaStreamWaitEvent(0, ev_join, 0);
}

// round 14
// speedup vs baseline: 1.0995x; 1.0995x over previous
#include <cuda_runtime.h>
#include <cuda_bf16.h>
#include <cuda_fp16.h>
#include <cstdint>
#include <cstddef>

#define BB    16
#define LQ    1024
#define EMBED 768
#define NH    12
#define NL    3
#define NP    4
#define DV    384
#define DH    32
#define LKV   5376
#define NOFF  288
#define NAW   144
#define NPK   432

// ---------------- scratch (device globals; no allocation) ----------------
__device__ __nv_bfloat16 g_qn   [(size_t)BB * LQ  * EMBED];
__device__ __half        g_kvn  [(size_t)BB * LKV * EMBED];
__device__ __half        g_value[(size_t)BB * LKV * DV];
__device__ float         g_offaw[(size_t)BB * LQ  * NPK];
__device__ __nv_bfloat16 g_attn [(size_t)BB * LQ  * DV];
__device__ __half        g_wv[EMBED * DV];
__device__ __nv_bfloat16 g_wc[EMBED * NPK];
__device__ __nv_bfloat16 g_wo[DV * EMBED];
__device__ float         g_bc[NPK];

// ---------------- fused LayerNorm (row=768) -> bf16 or fp16 ----------------
template <int FP16OUT>
__global__ void __launch_bounds__(192)
ln_kernel(const float* __restrict__ X, void* __restrict__ Yv,
          const float* __restrict__ w, const float* __restrict__ b) {
    int row = blockIdx.x;
    int tid = threadIdx.x;
    float4 v = ((const float4*)(X + (size_t)row * EMBED))[tid];
    float s  = v.x + v.y + v.z + v.w;
    float sq = v.x * v.x + v.y * v.y + v.z * v.z + v.w * v.w;
    #pragma unroll
    for (int o = 16; o > 0; o >>= 1) {
        s  += __shfl_down_sync(0xffffffffu, s,  o);
        sq += __shfl_down_sync(0xffffffffu, sq, o);
    }
    __shared__ float shs[6], shq[6];
    int wid = tid >> 5, lane = tid & 31;
    if (lane == 0) { shs[wid] = s; shq[wid] = sq; }
    __syncthreads();
    float ts = 0.f, tq = 0.f;
    #pragma unroll
    for (int i = 0; i < 6; i++) { ts += shs[i]; tq += shq[i]; }
    float mu = ts * (1.f / EMBED);
    float var = tq * (1.f / EMBED) - mu * mu;
    float rs = rsqrtf(var + 1e-6f);
    float4 w4 = ((const float4*)w)[tid];
    float4 b4 = ((const float4*)b)[tid];
    float2 f0 = make_float2((v.x - mu) * rs * w4.x + b4.x,
                            (v.y - mu) * rs * w4.y + b4.y);
    float2 f1 = make_float2((v.z - mu) * rs * w4.z + b4.z,
                            (v.w - mu) * rs * w4.w + b4.w);
    uint2 pk;
    if (FP16OUT) {
        __half2 p0 = __float22half2_rn(f0);
        __half2 p1 = __float22half2_rn(f1);
        pk = make_uint2(*(uint32_t*)&p0, *(uint32_t*)&p1);
    } else {
        __nv_bfloat162 p0 = __float22bfloat162_rn(f0);
        __nv_bfloat162 p1 = __float22bfloat162_rn(f1);
        pk = make_uint2(*(uint32_t*)&p0, *(uint32_t*)&p1);
    }
    ((uint2*)((char*)Yv + (size_t)row * EMBED * 2))[tid] = pk;
}

// ---------------- weight conversion / packing ----------------
__global__ void cvt16_kernel(const float* __restrict__ s,
                             __half* __restrict__ d, int n) {
    int i = blockIdx.x * blockDim.x + threadIdx.x;
    if (i < n) d[i] = __float2half(s[i]);
}
__global__ void cvt_kernel(const float* __restrict__ s,
                           __nv_bfloat16* __restrict__ d, int n) {
    int i = blockIdx.x * blockDim.x + threadIdx.x;
    if (i < n) d[i] = __float2bfloat16(s[i]);
}
__global__ void pack_kernel(const float* __restrict__ wo, const float* __restrict__ wa,
                            const float* __restrict__ bo, const float* __restrict__ ba,
                            __nv_bfloat16* __restrict__ d, float* __restrict__ bc) {
    int i = blockIdx.x * blockDim.x + threadIdx.x;
    if (i < EMBED * NPK) {
        int k = i / NPK, c = i % NPK;
        float v = (c < NOFF) ? wo[k * NOFF + c] : wa[k * NAW + c - NOFF];
        d[i] = __float2bfloat16(v);
    }
    if (i < NPK) bc[i] = (i < NOFF) ? bo[i] : ba[i - NOFF];
}

// ---------------- common GEMM helpers ----------------
__device__ __forceinline__ void ldsm_x4(uint32_t& r0, uint32_t& r1,
                                        uint32_t& r2, uint32_t& r3, uint32_t addr) {
    asm volatile("ldmatrix.sync.aligned.m8n8.x4.shared.b16 {%0,%1,%2,%3}, [%4];"
                 : "=r"(r0), "=r"(r1), "=r"(r2), "=r"(r3) : "r"(addr));
}
__device__ __forceinline__ void ldsm_x4_t(uint32_t& r0, uint32_t& r1,
                                          uint32_t& r2, uint32_t& r3, uint32_t addr) {
    asm volatile("ldmatrix.sync.aligned.m8n8.x4.trans.shared.b16 {%0,%1,%2,%3}, [%4];"
                 : "=r"(r0), "=r"(r1), "=r"(r2), "=r"(r3) : "r"(addr));
}
__device__ __forceinline__ void mma_bf16(float* c, const uint32_t* a,
                                         uint32_t b0, uint32_t b1) {
    asm volatile(
        "mma.sync.aligned.m16n8k16.row.col.f32.bf16.bf16.f32 "
        "{%0,%1,%2,%3}, {%4,%5,%6,%7}, {%8,%9}, {%0,%1,%2,%3};"
        : "+f"(c[0]), "+f"(c[1]), "+f"(c[2]), "+f"(c[3])
        : "r"(a[0]), "r"(a[1]), "r"(a[2]), "r"(a[3]), "r"(b0), "r"(b1));
}
__device__ __forceinline__ void mma_fp16(uint32_t* c, const uint32_t* a,
                                         uint32_t b0, uint32_t b1) {
    asm volatile(
        "mma.sync.aligned.m16n8k16.row.col.f16.f16.f16.f16 "
        "{%0,%1}, {%2,%3,%4,%5}, {%6,%7}, {%0,%1};"
        : "+r"(c[0]), "+r"(c[1])
        : "r"(a[0]), "r"(a[1]), "r"(a[2]), "r"(a[3]), "r"(b0), "r"(b1));
}
__device__ __forceinline__ void cp16(uint32_t s, const void* g) {
    asm volatile("cp.async.cg.shared.global [%0], [%1], 16;" :: "r"(s), "l"(g));
}
__device__ __forceinline__ void cp16z(uint32_t s, const void* g, bool pred) {
    int sz = pred ? 16 : 0;
    asm volatile("cp.async.cg.shared.global [%0], [%1], 16, %2;"
                 :: "r"(s), "l"(g), "r"(sz));
}
#define CP_COMMIT() asm volatile("cp.async.commit_group;" ::: "memory")
template <int N_>
__device__ __forceinline__ void cp_wait() {
    asm volatile("cp.async.wait_group %0;" :: "n"(N_) : "memory");
}

// ======== bf16 / f32-acc GEMM (offaw + out), 128x128 tile, BK=64 ========
#define SA 72
#define SB 136
#define STAGES 3
#define A_STG (128 * SA)
#define B_STG (64 * SB)
#define SMEM_BYTES ((STAGES * (A_STG + B_STG)) * 2)

// MODE 0: C fp32 = acc + bias;  MODE 1: C fp32 = resid + gamma*(acc+bias)
template <int MODE>
__global__ void __launch_bounds__(256, 2)
hgemm_kernel(const __nv_bfloat16* __restrict__ A,
             const __nv_bfloat16* __restrict__ Bm,
             void* __restrict__ Cout, int M, int N, int K,
             const float* __restrict__ bias,
             const float* __restrict__ resid, const float* __restrict__ gamma) {
    extern __shared__ __nv_bfloat16 smem[];
    __nv_bfloat16* sA = smem;
    __nv_bfloat16* sB = smem + STAGES * A_STG;

    const int tid  = threadIdx.x;
    const int lane = tid & 31;
    const int wid  = tid >> 5;
    const int wm   = wid & 3;
    const int wn   = wid >> 2;
    const int row0 = blockIdx.y * 128;
    const int n0   = blockIdx.x * 128;
    const int NT   = K >> 6;

    const uint32_t sAbase = (uint32_t)__cvta_generic_to_shared(sA);
    const uint32_t sBbase = (uint32_t)__cvta_generic_to_shared(sB);

    auto load_tile = [&](int stage, int kt) {
        const int k0 = kt * 64;
        #pragma unroll
        for (int j = 0; j < 4; j++) {
            int ci = tid + j * 256;
            int ar = ci >> 3, ac = (ci & 7) * 8;
            cp16(sAbase + (uint32_t)(stage * A_STG + ar * SA + ac) * 2,
                 A + (size_t)(row0 + ar) * K + k0 + ac);
            int br = ci >> 4, bc = (ci & 15) * 8;
            int col = n0 + bc;
            cp16z(sBbase + (uint32_t)(stage * B_STG + br * SB + bc) * 2,
                  Bm + (size_t)(k0 + br) * N + col, col < N);
        }
    };

    float acc[2][8][4];
    #pragma unroll
    for (int mt = 0; mt < 2; mt++)
        #pragma unroll
        for (int n8 = 0; n8 < 8; n8++)
            #pragma unroll
            for (int j = 0; j < 4; j++) acc[mt][n8][j] = 0.f;

    #pragma unroll
    for (int s = 0; s < STAGES - 1; s++) {
        if (s < NT) load_tile(s, s);
        CP_COMMIT();
    }

    const int lr  = lane & 15;
    const int lc8 = (lane >> 4) << 3;

    for (int kt = 0; kt < NT; kt++) {
        cp_wait<STAGES - 2>();
        __syncthreads();
        if (kt + STAGES - 1 < NT)
            load_tile((kt + STAGES - 1) % STAGES, kt + STAGES - 1);
        CP_COMMIT();

        const int cur = kt % STAGES;
        const uint32_t sAb = sAbase + (uint32_t)(cur * A_STG) * 2;
        const uint32_t sBb = sBbase + (uint32_t)(cur * B_STG) * 2;

        #pragma unroll
        for (int ks = 0; ks < 4; ks++) {
            const int kcol = ks * 16;
            uint32_t a[2][4];
            #pragma unroll
            for (int mt = 0; mt < 2; mt++) {
                uint32_t addr = sAb +
                    (uint32_t)((wm * 32 + mt * 16 + lr) * SA + kcol + lc8) * 2;
                ldsm_x4(a[mt][0], a[mt][1], a[mt][2], a[mt][3], addr);
            }
            uint32_t b[4][4];
            #pragma unroll
            for (int nt = 0; nt < 4; nt++) {
                uint32_t addr = sBb +
                    (uint32_t)((kcol + lr) * SB + wn * 64 + nt * 16 + lc8) * 2;
                ldsm_x4_t(b[nt][0], b[nt][1], b[nt][2], b[nt][3], addr);
            }
            #pragma unroll
            for (int mt = 0; mt < 2; mt++)
                #pragma unroll
                for (int n8 = 0; n8 < 8; n8++)
                    mma_bf16(acc[mt][n8], a[mt],
                             b[n8 >> 1][(n8 & 1) * 2], b[n8 >> 1][(n8 & 1) * 2 + 1]);
        }
    }

    #pragma unroll
    for (int mt = 0; mt < 2; mt++) {
        int r = row0 + wm * 32 + mt * 16 + (lane >> 2);
        #pragma unroll
        for (int n8 = 0; n8 < 8; n8++) {
            int c = n0 + wn * 64 + n8 * 8 + (lane & 3) * 2;
            if (c >= N) continue;
            float2 bs = *(const float2*)(bias + c);
            float v0 = acc[mt][n8][0] + bs.x;
            float v1 = acc[mt][n8][1] + bs.y;
            float v2 = acc[mt][n8][2] + bs.x;
            float v3 = acc[mt][n8][3] + bs.y;
            if (MODE == 1) {
                float2 gm = *(const float2*)(gamma + c);
                float2 r0v = *(const float2*)(resid + (size_t)r * N + c);
                float2 r1v = *(const float2*)(resid + (size_t)(r + 8) * N + c);
                float* Cf = (float*)Cout;
                *(float2*)(Cf + (size_t)r * N + c) =
                    make_float2(r0v.x + gm.x * v0, r0v.y + gm.y * v1);
                *(float2*)(Cf + (size_t)(r + 8) * N + c) =
                    make_float2(r1v.x + gm.x * v2, r1v.y + gm.y * v3);
            } else {
                float* Cf = (float*)Cout;
                *(float2*)(Cf + (size_t)r * N + c) = make_float2(v0, v1);
                *(float2*)(Cf + (size_t)(r + 8) * N + c) = make_float2(v2, v3);
            }
        }
    }
}

// ======== fp16 / fp16-acc GEMM (value), 256x128 tile, 64x64 warp tile ====
#define SA16 72
#define SB16 136
#define A_STG16 (256 * SA16)
#define B_STG16 (64 * SB16)
#define SMEM16_BYTES ((2 * (A_STG16 + B_STG16)) * 2)   // 2 stages

// C fp16 = acc + bias.  A [M,K] fp16, Bm [K,N] fp16, M%256==0, K%64==0.
__global__ void __launch_bounds__(256, 2)
hgemm16_kernel(const __half* __restrict__ A,
               const __half* __restrict__ Bm,
               __half* __restrict__ Cout, int M, int N, int K,
               const float* __restrict__ bias) {
    extern __shared__ __half smem16[];
    __half* sA = smem16;
    __half* sB = smem16 + 2 * A_STG16;

    const int tid  = threadIdx.x;
    const int lane = tid & 31;
    const int wid  = tid >> 5;
    const int wm   = wid & 3;       // 4 warp-rows of 64
    const int wn   = wid >> 2;      // 2 warp-cols of 64
    const int row0 = blockIdx.y * 256;
    const int n0   = blockIdx.x * 128;
    const int NT   = K >> 6;

    const uint32_t sAbase = (uint32_t)__cvta_generic_to_shared(sA);
    const uint32_t sBbase = (uint32_t)__cvta_generic_to_shared(sB);

    auto load_tile = [&](int stage, int kt) {
        const int k0 = kt * 64;
        #pragma unroll
        for (int j = 0; j < 8; j++) {            // A: 256x64 = 2048 chunks
            int ci = tid + j * 256;
            int ar = ci >> 3, ac = (ci & 7) * 8;
            cp16(sAbase + (uint32_t)(stage * A_STG16 + ar * SA16 + ac) * 2,
                 A + (size_t)(row0 + ar) * K + k0 + ac);
        }
        #pragma unroll
        for (int j = 0; j < 4; j++) {            // B: 64x128 = 1024 chunks
            int ci = tid + j * 256;
            int br = ci >> 4, bc = (ci & 15) * 8;
            int col = n0 + bc;
            cp16z(sBbase + (uint32_t)(stage * B_STG16 + br * SB16 + bc) * 2,
                  Bm + (size_t)(k0 + br) * N + col, col < N);
        }
    };

    uint32_t acc[4][8][2];
    #pragma unroll
    for (int mt = 0; mt < 4; mt++)
        #pragma unroll
        for (int n8 = 0; n8 < 8; n8++) {
            acc[mt][n8][0] = 0u; acc[mt][n8][1] = 0u;
        }

    load_tile(0, 0);
    CP_COMMIT();

    const int lr  = lane & 15;
    const int lc8 = (lane >> 4) << 3;

    for (int kt = 0; kt < NT; kt++) {
        cp_wait<0>();
        __syncthreads();                    // kt resident; prior compute done
        if (kt + 1 < NT) load_tile((kt + 1) & 1, kt + 1);
        CP_COMMIT();

        const int cur = kt & 1;
        const uint32_t sAb = sAbase + (uint32_t)(cur * A_STG16) * 2;
        const uint32_t sBb = sBbase + (uint32_t)(cur * B_STG16) * 2;

        #pragma unroll
        for (int ks = 0; ks < 4; ks++) {
            const int kcol = ks * 16;
            uint32_t a[4][4];
            #pragma unroll
            for (int mt = 0; mt < 4; mt++) {
                uint32_t addr = sAb +
                    (uint32_t)((wm * 64 + mt * 16 + lr) * SA16 + kcol + lc8) * 2;
                ldsm_x4(a[mt][0], a[mt][1], a[mt][2], a[mt][3], addr);
            }
            uint32_t b[4][4];
            #pragma unroll
            for (int nt = 0; nt < 4; nt++) {
                uint32_t addr = sBb +
                    (uint32_t)((kcol + lr) * SB16 + wn * 64 + nt * 16 + lc8) * 2;
                ldsm_x4_t(b[nt][0], b[nt][1], b[nt][2], b[nt][3], addr);
            }
            #pragma unroll
            for (int mt = 0; mt < 4; mt++)
                #pragma unroll
                for (int n8 = 0; n8 < 8; n8++)
                    mma_fp16(acc[mt][n8], a[mt],
                             b[n8 >> 1][(n8 & 1) * 2], b[n8 >> 1][(n8 & 1) * 2 + 1]);
        }
    }

    // epilogue: acc half2 + bias (fp32 math), store fp16
    #pragma unroll
    for (int mt = 0; mt < 4; mt++) {
        int r = row0 + wm * 64 + mt * 16 + (lane >> 2);
        #pragma unroll
        for (int n8 = 0; n8 < 8; n8++) {
            int c = n0 + wn * 64 + n8 * 8 + (lane & 3) * 2;
            if (c >= N) continue;
            float2 bs = *(const float2*)(bias + c);
            float2 f0 = __half22float2(*(__half2*)&acc[mt][n8][0]);
            float2 f1 = __half22float2(*(__half2*)&acc[mt][n8][1]);
            __half2 h0 = __float22half2_rn(make_float2(f0.x + bs.x, f0.y + bs.y));
            __half2 h1 = __float22half2_rn(make_float2(f1.x + bs.x, f1.y + bs.y));
            *(__half2*)(Cout + (size_t)r * N + c) = h0;
            *(__half2*)(Cout + (size_t)(r + 8) * N + c) = h1;
        }
    }
}

// ---------------- deformable bilinear sampling (per batch-half) ------------
__global__ void __launch_bounds__(256)
sample_kernel(const __half* __restrict__ value,          // (NB, LKV, NH*DH)
              const float* __restrict__ offaw,           // (NB*LQ, 432)
              const float* __restrict__ refp,            // (NB*LQ, NL, 2)
              __nv_bfloat16* __restrict__ attn)          // (NB*LQ, NH*DH)
{
    const int gw   = (blockIdx.x * blockDim.x + threadIdx.x) >> 5;
    const int lane = threadIdx.x & 31;
    const int cg   = lane >> 2;
    const int ch4  = lane & 3;
    const int h  = gw % NH;
    const int bq = gw / NH;
    const int b  = bq >> 10;

    const float* rowp = offaw + (size_t)bq * NPK;
    const float* lgp  = rowp + NOFF + h * (NL * NP);
    const float* op   = rowp + h * (NL * NP * 2);
    const float* rp   = refp + (size_t)bq * (NL * 2);

    float mx = -1e30f;
    #pragma unroll
    for (int i = 0; i < NL * NP; i++) mx = fmaxf(mx, lgp[i]);
    float ssum = 0.f;
    #pragma unroll
    for (int i = 0; i < NL * NP; i++) ssum += __expf(lgp[i] - mx);
    const float inv = 1.0f / ssum;

    float acc[8];
    #pragma unroll
    for (int j = 0; j < 8; j++) acc[j] = 0.f;

    const __half* vbb = value + (size_t)b * LKV * DV + h * DH;

    #pragma unroll
    for (int i = 0; i < 6; i++) {
        const int t      = i * 8 + cg;
        const int corner = t & 3;
        const int pt     = t >> 2;
        const int l      = pt >> 2;
        const int W      = 64 >> l;
        const int st     = (l == 0) ? 0 : ((l == 1) ? 4096 : 5120);

        const float rx = rp[l * 2 + 0], ry = rp[l * 2 + 1];
        const float ox = op[pt * 2 + 0], oy = op[pt * 2 + 1];
        const float invW = 1.0f / (float)W;
        const float xx = (rx + ox * invW) * (float)W - 0.5f;
        const float yy = (ry + oy * invW) * (float)W - 0.5f;
        const float x0f = floorf(xx), y0f = floorf(yy);
        const float dx = xx - x0f, dy = yy - y0f;
        const int xi = (int)x0f + (corner & 1);
        const int yi = (int)y0f + (corner >> 1);
        const float wx = (corner & 1) ? dx : 1.f - dx;
        const float wy = (corner >> 1) ? dy : 1.f - dy;
        const float wgt = __expf(lgp[pt] - mx) * inv * wx * wy;

        if (xi >= 0 && xi < W && yi >= 0 && yi < W) {
            const uint4* p = (const uint4*)(vbb + (size_t)(st + yi * W + xi) * DV) + ch4;
            uint4 v = *p;
            const __half2* h2 = (const __half2*)&v;
            #pragma unroll
            for (int j = 0; j < 4; j++) {
                float2 f = __half22float2(h2[j]);
                acc[2 * j]     = fmaf(wgt, f.x, acc[2 * j]);
                acc[2 * j + 1] = fmaf(wgt, f.y, acc[2 * j + 1]);
            }
        }
    }

    #pragma unroll
    for (int o = 4; o <= 16; o <<= 1)
        #pragma unroll
        for (int j = 0; j < 8; j++)
            acc[j] += __shfl_xor_sync(0xffffffffu, acc[j], o);

    if (cg == 0) {
        uint4 outv;
        uint32_t* ov = (uint32_t*)&outv;
        #pragma unroll
        for (int j = 0; j < 4; j++) {
            __nv_bfloat162 pk = __float22bfloat162_rn(
                make_float2(acc[2 * j], acc[2 * j + 1]));
            ov[j] = *(uint32_t*)&pk;
        }
        *(uint4*)(attn + (size_t)gw * DH + ch4 * 8) = outv;
    }
}

// ---------------- launch ----------------
extern "C" void kernel_launch(void* const* d_in, const int* in_sizes, int n_in,
                              void* d_out, int out_size) {
    const float* q      = (const float*)d_in[0];
    const float* refp   = (const float*)d_in[1];
    const float* kv     = (const float*)d_in[2];
    const float* ln1w   = (const float*)d_in[5];
    const float* ln1b   = (const float*)d_in[6];
    const float* ln2w   = (const float*)d_in[7];
    const float* ln2b   = (const float*)d_in[8];
    const float* gamma  = (const float*)d_in[9];
    const float* w_off  = (const float*)d_in[10];
    const float* b_off  = (const float*)d_in[11];
    const float* w_aw   = (const float*)d_in[12];
    const float* b_aw   = (const float*)d_in[13];
    const float* w_val  = (const float*)d_in[14];
    const float* b_val  = (const float*)d_in[15];
    const float* w_out  = (const float*)d_in[16];
    const float* b_out  = (const float*)d_in[17];
    float* out = (float*)d_out;

    __nv_bfloat16 *gqn, *gattn, *gwc, *gwo;
    __half *gkvn, *gv, *gwv;
    float *goffaw, *gbc;
    cudaGetSymbolAddress((void**)&gqn,    g_qn);
    cudaGetSymbolAddress((void**)&gkvn,   g_kvn);
    cudaGetSymbolAddress((void**)&gv,     g_value);
    cudaGetSymbolAddress((void**)&goffaw, g_offaw);
    cudaGetSymbolAddress((void**)&gattn,  g_attn);
    cudaGetSymbolAddress((void**)&gwv,    g_wv);
    cudaGetSymbolAddress((void**)&gwc,    g_wc);
    cudaGetSymbolAddress((void**)&gwo,    g_wo);
    cudaGetSymbolAddress((void**)&gbc,    g_bc);

    static cudaStream_t s_side = nullptr;
    static cudaEvent_t ev_w = nullptr, ev_join = nullptr;
    if (!s_side) {
        cudaStreamCreateWithFlags(&s_side, cudaStreamNonBlocking);
        cudaEventCreateWithFlags(&ev_w,    cudaEventDisableTiming);
        cudaEventCreateWithFlags(&ev_join, cudaEventDisableTiming);
        cudaFuncSetAttribute(hgemm_kernel<0>,
            cudaFuncAttributeMaxDynamicSharedMemorySize, SMEM_BYTES);
        cudaFuncSetAttribute(hgemm_kernel<1>,
            cudaFuncAttributeMaxDynamicSharedMemorySize, SMEM_BYTES);
        cudaFuncSetAttribute(hgemm16_kernel,
            cudaFuncAttributeMaxDynamicSharedMemorySize, SMEM16_BYTES);
    }

    const int HB   = BB / 2;          // 8 batches per half
    const int MqH  = HB * LQ;         // 8192
    const int MkvH = HB * LKV;        // 43008 (168 * 256)

    // ---- weight prep (short serial prefix on main stream) ----
    cvt16_kernel<<<(EMBED * DV + 255) / 256, 256>>>(w_val, gwv, EMBED * DV);
    pack_kernel<<<(EMBED * NPK + 255) / 256, 256>>>(
        w_off, w_aw, b_off, b_aw, gwc, gbc);
    cvt_kernel<<<(DV * EMBED + 255) / 256, 256>>>(w_out, gwo, DV * EMBED);
    cudaEventRecord(ev_w, 0);
    cudaStreamWaitEvent(s_side, ev_w, 0);

    // ---- per-half pipelines (half 0 on main, half 1 on side) ----
    for (int half = 0; half < 2; half++) {
        cudaStream_t st = (half == 0) ? (cudaStream_t)0 : s_side;
        const size_t qo  = (size_t)half * MqH;
        const size_t kvo = (size_t)half * MkvH;

        const float* qh    = q    + qo  * EMBED;
        const float* kvh   = kv   + kvo * EMBED;
        const float* refph = refp + qo  * NL * 2;
        __nv_bfloat16* qnh   = gqn   + qo  * EMBED;
        __half*        kvnh  = gkvn  + kvo * EMBED;
        __half*        gvh   = gv    + kvo * DV;
        float*         offh  = goffaw + qo * NPK;
        __nv_bfloat16* attnh = gattn + qo  * DV;
        float*         outh  = out   + qo  * EMBED;

        ln_kernel<0><<<MqH, 192, 0, st>>>(qh, qnh, ln1w, ln1b);
        ln_kernel<1><<<MkvH, 192, 0, st>>>(kvh, kvnh, ln2w, ln2b);

        // offaw: 8192 x 432, K=768 (bf16 / f32 acc)
        hgemm_kernel<0><<<dim3((NPK + 127) / 128, MqH / 128), 256, SMEM_BYTES, st>>>(
            qnh, gwc, offh, MqH, NPK, EMBED, gbc, nullptr, nullptr);

        // value: 43008 x 384, K=768 (fp16 / fp16 acc, 256x128 tile)
        hgemm16_kernel<<<dim3(DV / 128, MkvH / 256), 256, SMEM16_BYTES, st>>>(
            kvnh, gwv, gvh, MkvH, DV, EMBED, b_val);

        sample_kernel<<<(HB * LQ * NH) / 8, 256, 0, st>>>(
            gvh, offh, refph, attnh);

        // out: 8192 x 768, K=384 (bf16 / f32 acc)
        hgemm_kernel<1><<<dim3(EMBED / 128, MqH / 128), 256, SMEM_BYTES, st>>>(
            attnh, gwo, outh, MqH, EMBED, DV, b_out, qh, gamma);
    }

    cudaEventRecord(ev_join, s_side);
    cudaStreamWaitEvent(0, ev_join, 0);
}